// round 11
// baseline (speedup 1.0000x reference)
#include <cuda_runtime.h>
#include <math.h>

#define NN 100000
#define EE 1250000
#define H  64

// ---------------- scratch (static __device__ — zero-initialized at load) ----------------
// State-restoring pipeline: every run leaves g_degi/g_embed/g_asmax back at their
// zero-init values, so graph replays are deterministic without a prep kernel.
__device__ __align__(16) float g_bufA[NN * H];
__device__ __align__(16) float g_bufB[NN * H];
__device__ __align__(16) float g_t32 [NN * 32];
__device__ float g_dinv [NN];
__device__ float g_as   [NN];
__device__ float g_ad   [NN];
__device__ int   g_degi [NN];      // zeroed by k_scanB each run
__device__ int   g_scan [NN];
__device__ int   g_bsum [128];
__device__ int   g_row  [NN + 1];
__device__ int   g_cur  [NN];
__device__ int   g_csrc [EE];
__device__ int   g_asmax;          // reset to 0 by k_embed_final (0 = valid shift bound)
__device__ __align__(16) float g_embed[H];   // zeroed by k_embed_final

__device__ __forceinline__ float leaky(float v) { return v > 0.f ? v : 0.2f * v; }
__device__ __forceinline__ int enc_f(float f) {
    int i = __float_as_int(f);
    return i >= 0 ? i : (i ^ 0x7FFFFFFF);
}
__device__ __forceinline__ float dec_f(int i) {
    return __int_as_float(i >= 0 ? i : (i ^ 0x7FFFFFFF));
}

// ---------------- degree histogram ----------------
__global__ void k_deg(const int* __restrict__ dst, int e) {
    int t = blockIdx.x * blockDim.x + threadIdx.x;
    if (t < e) atomicAdd(&g_degi[dst[t]], 1);
}

// ---------------- scanA: per-1024-block inclusive scan + block sums ----------------
__global__ void __launch_bounds__(1024) k_scanA(int n) {
    __shared__ int wsum[32];
    int i = blockIdx.x * 1024 + threadIdx.x;
    int lane = threadIdx.x & 31, wid = threadIdx.x >> 5;
    int v = (i < n) ? g_degi[i] : 0;
    int s = v;
#pragma unroll
    for (int o = 1; o < 32; o <<= 1) {
        int u = __shfl_up_sync(0xffffffffu, s, o);
        if (lane >= o) s += u;
    }
    if (lane == 31) wsum[wid] = s;
    __syncthreads();
    if (wid == 0) {
        int w = wsum[lane];
#pragma unroll
        for (int o = 1; o < 32; o <<= 1) {
            int u = __shfl_up_sync(0xffffffffu, w, o);
            if (lane >= o) w += u;
        }
        wsum[lane] = w;
    }
    __syncthreads();
    int off = wid ? wsum[wid - 1] : 0;
    s += off;
    if (i < n) g_scan[i] = s;                        // inclusive within block
    if (threadIdx.x == 1023) g_bsum[blockIdx.x] = s; // block total
}

// ---------------- scanB: block-offset reduce + finalize row/cur/dinv, re-zero degi ----
__global__ void __launch_bounds__(1024) k_scanB(int n, int e) {
    __shared__ int s_off;
    int b = blockIdx.x;
    if (threadIdx.x < 32) {
        int lane = threadIdx.x;
        int acc = 0;
        for (int j = lane; j < b; j += 32) acc += g_bsum[j];
#pragma unroll
        for (int o = 16; o; o >>= 1) acc += __shfl_xor_sync(0xffffffffu, acc, o);
        if (lane == 0) s_off = acc;
    }
    __syncthreads();
    int i = b * 1024 + threadIdx.x;
    if (i < n) {
        int d = g_degi[i];
        int start = g_scan[i] - d + s_off;
        g_row[i] = start;
        g_cur[i] = start;
        g_dinv[i] = rsqrtf((float)(d + 1));   // +1 self-loop
        g_degi[i] = 0;                        // restore zero for next run
    }
    if (i == 0) g_row[n] = e;
}

__global__ void k_csr(const int* __restrict__ src, const int* __restrict__ dst, int e) {
    int t = blockIdx.x * blockDim.x + threadIdx.x;
    if (t >= e) return;
    int pos = atomicAdd(&g_cur[dst[t]], 1);
    g_csrc[pos] = src[t];
}

// ---------------- gather in F=32 space (8 lanes/node), unroll 4 ----------------
__global__ void __launch_bounds__(256) k_gather32(const float* __restrict__ x,
                                                  float* __restrict__ t, int n)
{
    int tt = blockIdx.x * blockDim.x + threadIdx.x;
    int node = tt >> 3;
    if (node >= n) return;
    int c = tt & 7;

    int beg = g_row[node], end = g_row[node + 1];
    float dd = g_dinv[node];
    float4 self = __ldg((const float4*)x + (size_t)node * 8 + c);
    float4 acc = make_float4(self.x * dd, self.y * dd, self.z * dd, self.w * dd);

    int i = beg;
    for (; i + 4 <= end; i += 4) {
        int s0 = __ldg(&g_csrc[i]);
        int s1 = __ldg(&g_csrc[i + 1]);
        int s2 = __ldg(&g_csrc[i + 2]);
        int s3 = __ldg(&g_csrc[i + 3]);
        float d0 = __ldg(&g_dinv[s0]);
        float d1 = __ldg(&g_dinv[s1]);
        float d2 = __ldg(&g_dinv[s2]);
        float d3 = __ldg(&g_dinv[s3]);
        float4 v0 = __ldg((const float4*)x + (size_t)s0 * 8 + c);
        float4 v1 = __ldg((const float4*)x + (size_t)s1 * 8 + c);
        float4 v2 = __ldg((const float4*)x + (size_t)s2 * 8 + c);
        float4 v3 = __ldg((const float4*)x + (size_t)s3 * 8 + c);
        acc.x += (d0 * v0.x + d1 * v1.x) + (d2 * v2.x + d3 * v3.x);
        acc.y += (d0 * v0.y + d1 * v1.y) + (d2 * v2.y + d3 * v3.y);
        acc.z += (d0 * v0.z + d1 * v1.z) + (d2 * v2.z + d3 * v3.z);
        acc.w += (d0 * v0.w + d1 * v1.w) + (d2 * v2.w + d3 * v3.w);
    }
    for (; i < end; i++) {
        int s0 = __ldg(&g_csrc[i]);
        float d0 = __ldg(&g_dinv[s0]);
        float4 v0 = __ldg((const float4*)x + (size_t)s0 * 8 + c);
        acc.x += d0 * v0.x; acc.y += d0 * v0.y;
        acc.z += d0 * v0.z; acc.w += d0 * v0.w;
    }
    ((float4*)t)[(size_t)node * 8 + c] = acc;
}

// ---------------- gather in H=64 space (16 lanes/node), unroll 4 ----------------
__global__ void __launch_bounds__(256) k_gather64(const float* __restrict__ h,
                                                  float* __restrict__ u, int n)
{
    int tt = blockIdx.x * blockDim.x + threadIdx.x;
    int node = tt >> 4;
    if (node >= n) return;
    int c = tt & 15;

    int beg = g_row[node], end = g_row[node + 1];
    float dd = g_dinv[node];
    float4 self = __ldg((const float4*)h + (size_t)node * 16 + c);
    float4 acc = make_float4(self.x * dd, self.y * dd, self.z * dd, self.w * dd);

    int i = beg;
    for (; i + 4 <= end; i += 4) {
        int s0 = __ldg(&g_csrc[i]);
        int s1 = __ldg(&g_csrc[i + 1]);
        int s2 = __ldg(&g_csrc[i + 2]);
        int s3 = __ldg(&g_csrc[i + 3]);
        float d0 = __ldg(&g_dinv[s0]);
        float d1 = __ldg(&g_dinv[s1]);
        float d2 = __ldg(&g_dinv[s2]);
        float d3 = __ldg(&g_dinv[s3]);
        float4 v0 = __ldg((const float4*)h + (size_t)s0 * 16 + c);
        float4 v1 = __ldg((const float4*)h + (size_t)s1 * 16 + c);
        float4 v2 = __ldg((const float4*)h + (size_t)s2 * 16 + c);
        float4 v3 = __ldg((const float4*)h + (size_t)s3 * 16 + c);
        acc.x += (d0 * v0.x + d1 * v1.x) + (d2 * v2.x + d3 * v3.x);
        acc.y += (d0 * v0.y + d1 * v1.y) + (d2 * v2.y + d3 * v3.y);
        acc.z += (d0 * v0.z + d1 * v1.z) + (d2 * v2.z + d3 * v3.z);
        acc.w += (d0 * v0.w + d1 * v1.w) + (d2 * v2.w + d3 * v3.w);
    }
    for (; i < end; i++) {
        int s0 = __ldg(&g_csrc[i]);
        float d0 = __ldg(&g_dinv[s0]);
        float4 v0 = __ldg((const float4*)h + (size_t)s0 * 16 + c);
        acc.x += d0 * v0.x; acc.y += d0 * v0.y;
        acc.z += d0 * v0.z; acc.w += d0 * v0.w;
    }
    ((float4*)u)[(size_t)node * 16 + c] = acc;
}

// ---------------- GEMM: [n,K] @ [K,64] ; 128 nodes/block, 256 threads ----------------
// MODE 0: out = relu(dinv[node]*(in @ W) + bias)   (GCN, aggregate-first)
// MODE 1: out = in @ W ; alpha dots ; global as-max (GAT)
template <int K, int MODE>
__global__ void __launch_bounds__(256) k_gemm(
    const float* __restrict__ in, const float* __restrict__ W,
    float* __restrict__ out, const float* __restrict__ bias,
    const float* __restrict__ avs, const float* __restrict__ avd, int n)
{
    constexpr int PAD = K + 1;                 // odd -> conflict-free
    __shared__ float Ws[K * H];
    __shared__ float xs[128 * PAD];
    __shared__ float as_s[H], ad_s[H], bs[H];
    __shared__ float smax[8];
    const int tid  = threadIdx.x;
    const int base = blockIdx.x * 128;

    for (int i = tid; i < K * H; i += 256) Ws[i] = W[i];
    if (MODE == 1 && tid < H) { as_s[tid] = avs[tid]; ad_s[tid] = avd[tid]; }
    if (MODE == 0 && tid < H) bs[tid] = bias[tid];

    int rows = n - base; if (rows > 128) rows = 128;
    for (int i = tid; i < rows * K; i += 256) {
        int r = i / K, c = i - r * K;
        xs[r * PAD + c] = in[(size_t)(base + r) * K + c];
    }
    __syncthreads();

    const int r     = tid >> 1;
    const bool valid = (r < rows);
    const int rc    = valid ? r : 0;
    const int half  = tid & 1;

    float acc[32];
#pragma unroll
    for (int j = 0; j < 32; j++) acc[j] = 0.f;

    const float* xrow = &xs[rc * PAD];
#pragma unroll 4
    for (int k = 0; k < K; k++) {
        float xv = xrow[k];
        const float4* w4 = (const float4*)&Ws[k * H];
#pragma unroll
        for (int j = 0; j < 8; j++) {
            float4 w = w4[j * 2 + half];
            acc[4*j+0] = fmaf(xv, w.x, acc[4*j+0]);
            acc[4*j+1] = fmaf(xv, w.y, acc[4*j+1]);
            acc[4*j+2] = fmaf(xv, w.z, acc[4*j+2]);
            acc[4*j+3] = fmaf(xv, w.w, acc[4*j+3]);
        }
    }

    const int node = base + r;
    if (MODE == 0) {
        if (!valid) return;
        float d = g_dinv[node];
        float4* o4 = (float4*)&out[(size_t)node * H];
#pragma unroll
        for (int j = 0; j < 8; j++) {
            int ch = (j * 2 + half) * 4;
            o4[j * 2 + half] = make_float4(
                fmaxf(fmaf(acc[4*j+0], d, bs[ch+0]), 0.f),
                fmaxf(fmaf(acc[4*j+1], d, bs[ch+1]), 0.f),
                fmaxf(fmaf(acc[4*j+2], d, bs[ch+2]), 0.f),
                fmaxf(fmaf(acc[4*j+3], d, bs[ch+3]), 0.f));
        }
    } else {
        float as = 0.f, ad = 0.f;
#pragma unroll
        for (int j = 0; j < 8; j++) {
#pragma unroll
            for (int q = 0; q < 4; q++) {
                int ch = (j * 2 + half) * 4 + q;
                as = fmaf(acc[4*j+q], as_s[ch], as);
                ad = fmaf(acc[4*j+q], ad_s[ch], ad);
            }
        }
        as += __shfl_xor_sync(0xffffffffu, as, 1);
        ad += __shfl_xor_sync(0xffffffffu, ad, 1);
        if (valid) {
            if (half == 0) { g_as[node] = as; g_ad[node] = ad; }
            float4* o4 = (float4*)&out[(size_t)node * H];
#pragma unroll
            for (int j = 0; j < 8; j++)
                o4[j * 2 + half] = make_float4(acc[4*j], acc[4*j+1], acc[4*j+2], acc[4*j+3]);
        }
        // block max of as -> one atomicMax per block (asmax starts at 0 each run;
        // 0 is a valid upper-bound shift if all as < 0, and exact otherwise)
        float amax = valid ? as : 0.f;
#pragma unroll
        for (int o = 16; o; o >>= 1)
            amax = fmaxf(amax, __shfl_xor_sync(0xffffffffu, amax, o));
        if ((tid & 31) == 0) smax[tid >> 5] = amax;
        __syncthreads();
        if (tid == 0) {
            float m = smax[0];
#pragma unroll
            for (int w = 1; w < 8; w++) m = fmaxf(m, smax[w]);
            if (m > 0.f) atomicMax(&g_asmax, enc_f(m));   // enc_f(m)>0 only matters vs init 0
        }
    }
}

// ---------------- GAT gather: single pass, global-max shift, unroll 4 ----------------
__global__ void __launch_bounds__(256) k_gat_gather(
    const float* __restrict__ h2, const float* __restrict__ b2,
    float* __restrict__ out, int n)
{
    int t = blockIdx.x * blockDim.x + threadIdx.x;
    int node = t >> 4;
    if (node >= n) return;
    int c = t & 15;

    int beg = g_row[node], end = g_row[node + 1];
    float ad_d  = g_ad[node];
    float M     = dec_f(g_asmax);            // upper bound of all as (>= 0 init)
    float m     = leaky(M + ad_d);           // >= every e on this node (leaky monotone)
    float eself = leaky(g_as[node] + ad_d);

    float4 acc = make_float4(0.f, 0.f, 0.f, 0.f);
    float den = 0.f;
    int i = beg;
    for (; i + 4 <= end; i += 4) {
        int s0 = __ldg(&g_csrc[i]);
        int s1 = __ldg(&g_csrc[i + 1]);
        int s2 = __ldg(&g_csrc[i + 2]);
        int s3 = __ldg(&g_csrc[i + 3]);
        float a0 = __ldg(&g_as[s0]);
        float a1 = __ldg(&g_as[s1]);
        float a2 = __ldg(&g_as[s2]);
        float a3 = __ldg(&g_as[s3]);
        float4 v0 = __ldg((const float4*)h2 + (size_t)s0 * 16 + c);
        float4 v1 = __ldg((const float4*)h2 + (size_t)s1 * 16 + c);
        float4 v2 = __ldg((const float4*)h2 + (size_t)s2 * 16 + c);
        float4 v3 = __ldg((const float4*)h2 + (size_t)s3 * 16 + c);
        float p0 = __expf(leaky(a0 + ad_d) - m);
        float p1 = __expf(leaky(a1 + ad_d) - m);
        float p2 = __expf(leaky(a2 + ad_d) - m);
        float p3 = __expf(leaky(a3 + ad_d) - m);
        acc.x += (p0 * v0.x + p1 * v1.x) + (p2 * v2.x + p3 * v3.x);
        acc.y += (p0 * v0.y + p1 * v1.y) + (p2 * v2.y + p3 * v3.y);
        acc.z += (p0 * v0.z + p1 * v1.z) + (p2 * v2.z + p3 * v3.z);
        acc.w += (p0 * v0.w + p1 * v1.w) + (p2 * v2.w + p3 * v3.w);
        den += (p0 + p1) + (p2 + p3);
    }
    for (; i < end; i++) {
        int s0 = __ldg(&g_csrc[i]);
        float p0 = __expf(leaky(__ldg(&g_as[s0]) + ad_d) - m);
        float4 v0 = __ldg((const float4*)h2 + (size_t)s0 * 16 + c);
        acc.x += p0 * v0.x; acc.y += p0 * v0.y;
        acc.z += p0 * v0.z; acc.w += p0 * v0.w;
        den += p0;
    }

    float pself = __expf(eself - m);
    float w = 1.f / (den + pself);
    float4 hd = __ldg((const float4*)h2 + (size_t)node * 16 + c);
    float4 bb = __ldg((const float4*)b2 + c);
    float4 rr;
    rr.x = fmaxf(fmaf(acc.x + pself * hd.x, w, bb.x), 0.f);
    rr.y = fmaxf(fmaf(acc.y + pself * hd.y, w, bb.y), 0.f);
    rr.z = fmaxf(fmaf(acc.z + pself * hd.z, w, bb.z), 0.f);
    rr.w = fmaxf(fmaf(acc.w + pself * hd.w, w, bb.w), 0.f);
    ((float4*)&out[(size_t)node * H])[c] = rr;
}

// ---------------- GEMM3 + heads fused: h3 = relu(dinv*(u@W3)+b3); opt/bottleneck/embed ----
__global__ void __launch_bounds__(256) k_gemm3_heads(
    const float* __restrict__ in, const float* __restrict__ W,
    const float* __restrict__ b3,
    const float* __restrict__ Wopt, const float* __restrict__ bopt,
    const float* __restrict__ Wb1,  const float* __restrict__ bb1,
    const float* __restrict__ Wb2,  const float* __restrict__ bb2,
    float* __restrict__ out_opt, float* __restrict__ out_bot, int n)
{
    constexpr int K = 64, PAD = K + 1;
    __shared__ float Ws[K * H];
    __shared__ float xs[128 * PAD];
    __shared__ float bs[H];
    __shared__ float sWopt[H * 10], sbopt[10], sWb1[H * 32], sbb1[32], sWb2[32], sbb2[1];
    __shared__ float sEmb[H];
    const int tid  = threadIdx.x;
    const int base = blockIdx.x * 128;

    for (int i = tid; i < K * H; i += 256) Ws[i] = W[i];
    for (int i = tid; i < H * 10; i += 256) sWopt[i] = Wopt[i];
    for (int i = tid; i < H * 32; i += 256) sWb1[i] = Wb1[i];
    if (tid < H)  { bs[tid] = b3[tid]; sEmb[tid] = 0.f; }
    if (tid < 32) { sbb1[tid] = bb1[tid]; sWb2[tid] = Wb2[tid]; }
    if (tid < 10) sbopt[tid] = bopt[tid];
    if (tid == 0) sbb2[0] = bb2[0];

    int rows = n - base; if (rows > 128) rows = 128;
    for (int i = tid; i < rows * K; i += 256) {
        int r = i / K, c = i - r * K;
        xs[r * PAD + c] = in[(size_t)(base + r) * K + c];
    }
    __syncthreads();

    const int r     = tid >> 1;
    const bool valid = (r < rows);
    const int rc    = valid ? r : 0;
    const int half  = tid & 1;

    float acc[32];
#pragma unroll
    for (int j = 0; j < 32; j++) acc[j] = 0.f;

    const float* xrow = &xs[rc * PAD];
#pragma unroll 4
    for (int k = 0; k < K; k++) {
        float xv = xrow[k];
        const float4* w4 = (const float4*)&Ws[k * H];
#pragma unroll
        for (int j = 0; j < 8; j++) {
            float4 w = w4[j * 2 + half];
            acc[4*j+0] = fmaf(xv, w.x, acc[4*j+0]);
            acc[4*j+1] = fmaf(xv, w.y, acc[4*j+1]);
            acc[4*j+2] = fmaf(xv, w.z, acc[4*j+2]);
            acc[4*j+3] = fmaf(xv, w.w, acc[4*j+3]);
        }
    }

    const int node = base + r;
    float d = valid ? g_dinv[node] : 0.f;

    // h3 in place of acc: relu(d*acc + b3[ch]); force 0 for invalid threads
#pragma unroll
    for (int j = 0; j < 8; j++) {
#pragma unroll
        for (int q = 0; q < 4; q++) {
            int ch = (j * 2 + half) * 4 + q;
            float v = fmaxf(fmaf(acc[4*j+q], d, bs[ch]), 0.f);
            acc[4*j+q] = valid ? v : 0.f;
        }
    }

    // opt logits: 10 dots, combine halves via shfl
#pragma unroll
    for (int c = 0; c < 10; c++) {
        float p = 0.f;
#pragma unroll
        for (int j = 0; j < 8; j++) {
#pragma unroll
            for (int q = 0; q < 4; q++) {
                int ch = (j * 2 + half) * 4 + q;
                p = fmaf(acc[4*j+q], sWopt[ch * 10 + c], p);
            }
        }
        p += __shfl_xor_sync(0xffffffffu, p, 1);
        if (valid && half == 0) out_opt[(size_t)node * 10 + c] = p + sbopt[c];
    }

    // bottleneck MLP
    float z = 0.f;
#pragma unroll
    for (int m = 0; m < 32; m++) {
        float s = 0.f;
#pragma unroll
        for (int j = 0; j < 8; j++) {
#pragma unroll
            for (int q = 0; q < 4; q++) {
                int ch = (j * 2 + half) * 4 + q;
                s = fmaf(acc[4*j+q], sWb1[ch * 32 + m], s);
            }
        }
        s += __shfl_xor_sync(0xffffffffu, s, 1);
        z = fmaf(fmaxf(s + sbb1[m], 0.f), sWb2[m], z);
    }
    if (valid && half == 0) out_bot[node] = 1.f / (1.f + expf(-(z + sbb2[0])));

    // embedding: parity-preserving warp reduce, then smem, then global
    const int lane = tid & 31;
#pragma unroll
    for (int idx = 0; idx < 32; idx++) {
        float v = acc[idx];
        v += __shfl_xor_sync(0xffffffffu, v, 2);
        v += __shfl_xor_sync(0xffffffffu, v, 4);
        v += __shfl_xor_sync(0xffffffffu, v, 8);
        v += __shfl_xor_sync(0xffffffffu, v, 16);
        if (lane < 2) {
            int ch = ((idx >> 2) * 2 + half) * 4 + (idx & 3);
            atomicAdd(&sEmb[ch], v);
        }
    }
    __syncthreads();
    if (tid < H) atomicAdd(&g_embed[tid], sEmb[tid]);
}

__global__ void k_embed_final(float* __restrict__ emb_out, float inv_n) {
    int t = threadIdx.x;
    if (t < H) {
        emb_out[t] = g_embed[t] * inv_n;
        g_embed[t] = 0.f;                 // restore zero for next run
    }
    if (t == 0) g_asmax = 0;              // restore init for next run
}

// ---------------- launcher ----------------
extern "C" void kernel_launch(void* const* d_in, const int* in_sizes, int n_in,
                              void* d_out, int out_size)
{
    const float* x    = (const float*)d_in[0];
    const int*   ei   = (const int*)  d_in[1];
    const float* W1   = (const float*)d_in[2];
    const float* b1   = (const float*)d_in[3];
    const float* W2   = (const float*)d_in[4];
    const float* avs  = (const float*)d_in[5];
    const float* avd  = (const float*)d_in[6];
    const float* b2   = (const float*)d_in[7];
    const float* W3   = (const float*)d_in[8];
    const float* b3   = (const float*)d_in[9];
    const float* Wopt = (const float*)d_in[10];
    const float* bopt = (const float*)d_in[11];
    const float* Wb1  = (const float*)d_in[12];
    const float* bb1  = (const float*)d_in[13];
    const float* Wb2  = (const float*)d_in[14];
    const float* bb2  = (const float*)d_in[15];

    const int n = in_sizes[0] / 32;   // F = 32
    const int e = in_sizes[1] / 2;
    const int* src = ei;
    const int* dst = ei + e;

    float* out_opt = (float*)d_out;
    float* out_bot = out_opt + (size_t)n * 10;
    float* out_emb = out_bot + n;

    float *bufA = nullptr, *bufB = nullptr, *t32 = nullptr;
    cudaGetSymbolAddress((void**)&bufA, g_bufA);
    cudaGetSymbolAddress((void**)&bufB, g_bufB);
    cudaGetSymbolAddress((void**)&t32,  g_t32);

    const int B = 256;
    const int gE   = (e + B - 1) / B;
    const int gN8  = (n * 8  + B - 1) / B;
    const int gN16 = (n * 16 + B - 1) / B;
    const int gG   = (n + 127) / 128;
    const int nb   = (n + 1023) / 1024;

    // CSR build: degree histogram -> 2-kernel scan/finalize -> cursor scatter
    k_deg<<<gE, B>>>(dst, e);                 // #1
    k_scanA<<<nb, 1024>>>(n);                 // #2
    k_scanB<<<nb, 1024>>>(n, e);              // #3
    k_csr<<<gE, B>>>(src, dst, e);            // #4

    // GCN layer 1: aggregate in F=32 space, then transform
    k_gather32<<<gN8, B>>>(x, t32, n);        // #5
    k_gemm<32, 0><<<gG, 256>>>(t32, W1, bufB, b1, nullptr, nullptr, n);   // #6 (ncu window)

    // GAT layer (single-pass softmax via global as-max)
    k_gemm<64, 1><<<gG, 256>>>(bufB, W2, bufA, nullptr, avs, avd, n);     // #7
    k_gat_gather<<<gN16, B>>>(bufA, b2, bufB, n);                         // #8

    // GCN layer 3: aggregate-first, then fused transform + heads
    k_gather64<<<gN16, B>>>(bufB, bufA, n);                               // #9
    k_gemm3_heads<<<gG, 256>>>(bufA, W3, b3, Wopt, bopt, Wb1, bb1, Wb2, bb2,
                               out_opt, out_bot, n);                      // #10

    k_embed_final<<<1, 64>>>(out_emb, 1.0f / (float)n);                   // #11
}

// round 12
// speedup vs baseline: 1.0311x; 1.0311x over previous
#include <cuda_runtime.h>
#include <math.h>

#define NN 100000
#define EE 1250000
#define H  64

typedef unsigned long long u64;

// ---------------- scratch (static __device__ — zero-initialized at load) ----------------
__device__ __align__(16) float g_bufA[NN * H];
__device__ __align__(16) float g_bufB[NN * H];
__device__ __align__(16) float g_t32 [NN * 32];
__device__ float g_dinv [NN];
__device__ float g_as   [NN];
__device__ float g_ad   [NN];
__device__ int   g_degi [NN];      // zeroed by k_scanB each run
__device__ int   g_scan [NN];
__device__ int   g_bsum [128];
__device__ int   g_row  [NN + 1];
__device__ int   g_cur  [NN];
__device__ int   g_csrc [EE];
__device__ int   g_asmax;          // reset to 0 by k_embed_final
__device__ __align__(16) float g_embed[H];   // zeroed by k_embed_final

__device__ __forceinline__ float leaky(float v) { return v > 0.f ? v : 0.2f * v; }
__device__ __forceinline__ int enc_f(float f) {
    int i = __float_as_int(f);
    return i >= 0 ? i : (i ^ 0x7FFFFFFF);
}
__device__ __forceinline__ float dec_f(int i) {
    return __int_as_float(i >= 0 ? i : (i ^ 0x7FFFFFFF));
}

// ---------------- f32x2 packed helpers ----------------
__device__ __forceinline__ u64 pack2(float lo, float hi) {
    u64 d; asm("mov.b64 %0, {%1, %2};" : "=l"(d) : "f"(lo), "f"(hi)); return d;
}
__device__ __forceinline__ void unpack2(u64 v, float& lo, float& hi) {
    asm("mov.b64 {%0, %1}, %2;" : "=f"(lo), "=f"(hi) : "l"(v));
}
__device__ __forceinline__ u64 fma2(u64 a, u64 b, u64 c) {
    u64 d; asm("fma.rn.f32x2 %0, %1, %2, %3;" : "=l"(d) : "l"(a), "l"(b), "l"(c)); return d;
}

// ---------------- degree histogram: 4 edges/thread (MLP=4) ----------------
__global__ void k_deg(const int* __restrict__ dst, int e) {
    int base = (blockIdx.x * blockDim.x + threadIdx.x) * 4;
#pragma unroll
    for (int j = 0; j < 4; j++) {
        int i = base + j;
        if (i < e) atomicAdd(&g_degi[__ldg(&dst[i])], 1);
    }
}

// ---------------- scanA: per-1024-block inclusive scan + block sums ----------------
__global__ void __launch_bounds__(1024) k_scanA(int n) {
    __shared__ int wsum[32];
    int i = blockIdx.x * 1024 + threadIdx.x;
    int lane = threadIdx.x & 31, wid = threadIdx.x >> 5;
    int v = (i < n) ? g_degi[i] : 0;
    int s = v;
#pragma unroll
    for (int o = 1; o < 32; o <<= 1) {
        int u = __shfl_up_sync(0xffffffffu, s, o);
        if (lane >= o) s += u;
    }
    if (lane == 31) wsum[wid] = s;
    __syncthreads();
    if (wid == 0) {
        int w = wsum[lane];
#pragma unroll
        for (int o = 1; o < 32; o <<= 1) {
            int u = __shfl_up_sync(0xffffffffu, w, o);
            if (lane >= o) w += u;
        }
        wsum[lane] = w;
    }
    __syncthreads();
    int off = wid ? wsum[wid - 1] : 0;
    s += off;
    if (i < n) g_scan[i] = s;
    if (threadIdx.x == 1023) g_bsum[blockIdx.x] = s;
}

// ---------------- scanB: block-offset reduce + finalize row/cur/dinv, re-zero degi ----
__global__ void __launch_bounds__(1024) k_scanB(int n, int e) {
    __shared__ int s_off;
    int b = blockIdx.x;
    if (threadIdx.x < 32) {
        int lane = threadIdx.x;
        int acc = 0;
        for (int j = lane; j < b; j += 32) acc += g_bsum[j];
#pragma unroll
        for (int o = 16; o; o >>= 1) acc += __shfl_xor_sync(0xffffffffu, acc, o);
        if (lane == 0) s_off = acc;
    }
    __syncthreads();
    int i = b * 1024 + threadIdx.x;
    if (i < n) {
        int d = g_degi[i];
        int start = g_scan[i] - d + s_off;
        g_row[i] = start;
        g_cur[i] = start;
        g_dinv[i] = rsqrtf((float)(d + 1));
        g_degi[i] = 0;
    }
    if (i == 0) g_row[n] = e;
}

// ---------------- CSR scatter: 4 edges/thread (MLP=4) ----------------
__global__ void k_csr(const int* __restrict__ src, const int* __restrict__ dst, int e) {
    int base = (blockIdx.x * blockDim.x + threadIdx.x) * 4;
#pragma unroll
    for (int j = 0; j < 4; j++) {
        int i = base + j;
        if (i < e) {
            int pos = atomicAdd(&g_cur[__ldg(&dst[i])], 1);
            g_csrc[pos] = __ldg(&src[i]);
        }
    }
}

// ---------------- gather in F=32 space (8 lanes/node), unroll 4 ----------------
__global__ void __launch_bounds__(256) k_gather32(const float* __restrict__ x,
                                                  float* __restrict__ t, int n)
{
    int tt = blockIdx.x * blockDim.x + threadIdx.x;
    int node = tt >> 3;
    if (node >= n) return;
    int c = tt & 7;

    int beg = g_row[node], end = g_row[node + 1];
    float dd = g_dinv[node];
    float4 self = __ldg((const float4*)x + (size_t)node * 8 + c);
    float4 acc = make_float4(self.x * dd, self.y * dd, self.z * dd, self.w * dd);

    int i = beg;
    for (; i + 4 <= end; i += 4) {
        int s0 = __ldg(&g_csrc[i]);
        int s1 = __ldg(&g_csrc[i + 1]);
        int s2 = __ldg(&g_csrc[i + 2]);
        int s3 = __ldg(&g_csrc[i + 3]);
        float d0 = __ldg(&g_dinv[s0]);
        float d1 = __ldg(&g_dinv[s1]);
        float d2 = __ldg(&g_dinv[s2]);
        float d3 = __ldg(&g_dinv[s3]);
        float4 v0 = __ldg((const float4*)x + (size_t)s0 * 8 + c);
        float4 v1 = __ldg((const float4*)x + (size_t)s1 * 8 + c);
        float4 v2 = __ldg((const float4*)x + (size_t)s2 * 8 + c);
        float4 v3 = __ldg((const float4*)x + (size_t)s3 * 8 + c);
        acc.x += (d0 * v0.x + d1 * v1.x) + (d2 * v2.x + d3 * v3.x);
        acc.y += (d0 * v0.y + d1 * v1.y) + (d2 * v2.y + d3 * v3.y);
        acc.z += (d0 * v0.z + d1 * v1.z) + (d2 * v2.z + d3 * v3.z);
        acc.w += (d0 * v0.w + d1 * v1.w) + (d2 * v2.w + d3 * v3.w);
    }
    for (; i < end; i++) {
        int s0 = __ldg(&g_csrc[i]);
        float d0 = __ldg(&g_dinv[s0]);
        float4 v0 = __ldg((const float4*)x + (size_t)s0 * 8 + c);
        acc.x += d0 * v0.x; acc.y += d0 * v0.y;
        acc.z += d0 * v0.z; acc.w += d0 * v0.w;
    }
    ((float4*)t)[(size_t)node * 8 + c] = acc;
}

// ---------------- gather in H=64 space (16 lanes/node), unroll 4 ----------------
__global__ void __launch_bounds__(256) k_gather64(const float* __restrict__ h,
                                                  float* __restrict__ u, int n)
{
    int tt = blockIdx.x * blockDim.x + threadIdx.x;
    int node = tt >> 4;
    if (node >= n) return;
    int c = tt & 15;

    int beg = g_row[node], end = g_row[node + 1];
    float dd = g_dinv[node];
    float4 self = __ldg((const float4*)h + (size_t)node * 16 + c);
    float4 acc = make_float4(self.x * dd, self.y * dd, self.z * dd, self.w * dd);

    int i = beg;
    for (; i + 4 <= end; i += 4) {
        int s0 = __ldg(&g_csrc[i]);
        int s1 = __ldg(&g_csrc[i + 1]);
        int s2 = __ldg(&g_csrc[i + 2]);
        int s3 = __ldg(&g_csrc[i + 3]);
        float d0 = __ldg(&g_dinv[s0]);
        float d1 = __ldg(&g_dinv[s1]);
        float d2 = __ldg(&g_dinv[s2]);
        float d3 = __ldg(&g_dinv[s3]);
        float4 v0 = __ldg((const float4*)h + (size_t)s0 * 16 + c);
        float4 v1 = __ldg((const float4*)h + (size_t)s1 * 16 + c);
        float4 v2 = __ldg((const float4*)h + (size_t)s2 * 16 + c);
        float4 v3 = __ldg((const float4*)h + (size_t)s3 * 16 + c);
        acc.x += (d0 * v0.x + d1 * v1.x) + (d2 * v2.x + d3 * v3.x);
        acc.y += (d0 * v0.y + d1 * v1.y) + (d2 * v2.y + d3 * v3.y);
        acc.z += (d0 * v0.z + d1 * v1.z) + (d2 * v2.z + d3 * v3.z);
        acc.w += (d0 * v0.w + d1 * v1.w) + (d2 * v2.w + d3 * v3.w);
    }
    for (; i < end; i++) {
        int s0 = __ldg(&g_csrc[i]);
        float d0 = __ldg(&g_dinv[s0]);
        float4 v0 = __ldg((const float4*)h + (size_t)s0 * 16 + c);
        acc.x += d0 * v0.x; acc.y += d0 * v0.y;
        acc.z += d0 * v0.z; acc.w += d0 * v0.w;
    }
    ((float4*)u)[(size_t)node * 16 + c] = acc;
}

// ---------------- GEMM (f32x2 mainloop): [n,K] @ [K,64] ; 128 nodes/block, 256 thr ----
// MODE 0: out = relu(dinv[node]*(in @ W) + bias)
// MODE 1: out = in @ W ; alpha dots ; global as-max
template <int K, int MODE>
__global__ void __launch_bounds__(256) k_gemm(
    const float* __restrict__ in, const float* __restrict__ W,
    float* __restrict__ out, const float* __restrict__ bias,
    const float* __restrict__ avs, const float* __restrict__ avd, int n)
{
    constexpr int PAD = K + 1;
    __shared__ __align__(16) float Ws[K * H];
    __shared__ float xs[128 * PAD];
    __shared__ float as_s[H], ad_s[H], bs[H];
    __shared__ float smax[8];
    const int tid  = threadIdx.x;
    const int base = blockIdx.x * 128;

    for (int i = tid; i < K * H; i += 256) Ws[i] = W[i];
    if (MODE == 1 && tid < H) { as_s[tid] = avs[tid]; ad_s[tid] = avd[tid]; }
    if (MODE == 0 && tid < H) bs[tid] = bias[tid];

    int rows = n - base; if (rows > 128) rows = 128;
    for (int i = tid; i < rows * K; i += 256) {
        int r = i / K, c = i - r * K;
        xs[r * PAD + c] = in[(size_t)(base + r) * K + c];
    }
    __syncthreads();

    const int r     = tid >> 1;
    const bool valid = (r < rows);
    const int rc    = valid ? r : 0;
    const int half  = tid & 1;

    u64 acc2[16];
#pragma unroll
    for (int j = 0; j < 16; j++) acc2[j] = 0ull;

    const float* xrow = &xs[rc * PAD];
    // thread's W view: element (k*16 + j*2 + half) in ulonglong2 units
    const ulonglong2* w2 = (const ulonglong2*)Ws;
#pragma unroll 4
    for (int k = 0; k < K; k++) {
        float xv = xrow[k];
        u64 xv2 = pack2(xv, xv);
        const ulonglong2* wk = w2 + k * 16 + half;
#pragma unroll
        for (int j = 0; j < 8; j++) {
            ulonglong2 wv = wk[j * 2];
            acc2[2*j]   = fma2(xv2, wv.x, acc2[2*j]);
            acc2[2*j+1] = fma2(xv2, wv.y, acc2[2*j+1]);
        }
    }

    float acc[32];
#pragma unroll
    for (int j = 0; j < 16; j++) unpack2(acc2[j], acc[2*j], acc[2*j+1]);

    const int node = base + r;
    if (MODE == 0) {
        if (!valid) return;
        float d = g_dinv[node];
        float4* o4 = (float4*)&out[(size_t)node * H];
#pragma unroll
        for (int j = 0; j < 8; j++) {
            int ch = (j * 2 + half) * 4;
            o4[j * 2 + half] = make_float4(
                fmaxf(fmaf(acc[4*j+0], d, bs[ch+0]), 0.f),
                fmaxf(fmaf(acc[4*j+1], d, bs[ch+1]), 0.f),
                fmaxf(fmaf(acc[4*j+2], d, bs[ch+2]), 0.f),
                fmaxf(fmaf(acc[4*j+3], d, bs[ch+3]), 0.f));
        }
    } else {
        float as = 0.f, ad = 0.f;
#pragma unroll
        for (int j = 0; j < 8; j++) {
#pragma unroll
            for (int q = 0; q < 4; q++) {
                int ch = (j * 2 + half) * 4 + q;
                as = fmaf(acc[4*j+q], as_s[ch], as);
                ad = fmaf(acc[4*j+q], ad_s[ch], ad);
            }
        }
        as += __shfl_xor_sync(0xffffffffu, as, 1);
        ad += __shfl_xor_sync(0xffffffffu, ad, 1);
        if (valid) {
            if (half == 0) { g_as[node] = as; g_ad[node] = ad; }
            float4* o4 = (float4*)&out[(size_t)node * H];
#pragma unroll
            for (int j = 0; j < 8; j++)
                o4[j * 2 + half] = make_float4(acc[4*j], acc[4*j+1], acc[4*j+2], acc[4*j+3]);
        }
        float amax = valid ? as : 0.f;
#pragma unroll
        for (int o = 16; o; o >>= 1)
            amax = fmaxf(amax, __shfl_xor_sync(0xffffffffu, amax, o));
        if ((tid & 31) == 0) smax[tid >> 5] = amax;
        __syncthreads();
        if (tid == 0) {
            float m = smax[0];
#pragma unroll
            for (int w = 1; w < 8; w++) m = fmaxf(m, smax[w]);
            if (m > 0.f) atomicMax(&g_asmax, enc_f(m));
        }
    }
}

// ---------------- GAT gather: single pass, global-max shift, unroll 4 ----------------
__global__ void __launch_bounds__(256) k_gat_gather(
    const float* __restrict__ h2, const float* __restrict__ b2,
    float* __restrict__ out, int n)
{
    int t = blockIdx.x * blockDim.x + threadIdx.x;
    int node = t >> 4;
    if (node >= n) return;
    int c = t & 15;

    int beg = g_row[node], end = g_row[node + 1];
    float ad_d  = g_ad[node];
    float M     = dec_f(g_asmax);
    float m     = leaky(M + ad_d);
    float eself = leaky(g_as[node] + ad_d);

    float4 acc = make_float4(0.f, 0.f, 0.f, 0.f);
    float den = 0.f;
    int i = beg;
    for (; i + 4 <= end; i += 4) {
        int s0 = __ldg(&g_csrc[i]);
        int s1 = __ldg(&g_csrc[i + 1]);
        int s2 = __ldg(&g_csrc[i + 2]);
        int s3 = __ldg(&g_csrc[i + 3]);
        float a0 = __ldg(&g_as[s0]);
        float a1 = __ldg(&g_as[s1]);
        float a2 = __ldg(&g_as[s2]);
        float a3 = __ldg(&g_as[s3]);
        float4 v0 = __ldg((const float4*)h2 + (size_t)s0 * 16 + c);
        float4 v1 = __ldg((const float4*)h2 + (size_t)s1 * 16 + c);
        float4 v2 = __ldg((const float4*)h2 + (size_t)s2 * 16 + c);
        float4 v3 = __ldg((const float4*)h2 + (size_t)s3 * 16 + c);
        float p0 = __expf(leaky(a0 + ad_d) - m);
        float p1 = __expf(leaky(a1 + ad_d) - m);
        float p2 = __expf(leaky(a2 + ad_d) - m);
        float p3 = __expf(leaky(a3 + ad_d) - m);
        acc.x += (p0 * v0.x + p1 * v1.x) + (p2 * v2.x + p3 * v3.x);
        acc.y += (p0 * v0.y + p1 * v1.y) + (p2 * v2.y + p3 * v3.y);
        acc.z += (p0 * v0.z + p1 * v1.z) + (p2 * v2.z + p3 * v3.z);
        acc.w += (p0 * v0.w + p1 * v1.w) + (p2 * v2.w + p3 * v3.w);
        den += (p0 + p1) + (p2 + p3);
    }
    for (; i < end; i++) {
        int s0 = __ldg(&g_csrc[i]);
        float p0 = __expf(leaky(__ldg(&g_as[s0]) + ad_d) - m);
        float4 v0 = __ldg((const float4*)h2 + (size_t)s0 * 16 + c);
        acc.x += p0 * v0.x; acc.y += p0 * v0.y;
        acc.z += p0 * v0.z; acc.w += p0 * v0.w;
        den += p0;
    }

    float pself = __expf(eself - m);
    float w = 1.f / (den + pself);
    float4 hd = __ldg((const float4*)h2 + (size_t)node * 16 + c);
    float4 bb = __ldg((const float4*)b2 + c);
    float4 rr;
    rr.x = fmaxf(fmaf(acc.x + pself * hd.x, w, bb.x), 0.f);
    rr.y = fmaxf(fmaf(acc.y + pself * hd.y, w, bb.y), 0.f);
    rr.z = fmaxf(fmaf(acc.z + pself * hd.z, w, bb.z), 0.f);
    rr.w = fmaxf(fmaf(acc.w + pself * hd.w, w, bb.w), 0.f);
    ((float4*)&out[(size_t)node * H])[c] = rr;
}

// ---------------- GEMM3 + heads (f32x2 mainloop + packed head dots) ----------------
__global__ void __launch_bounds__(256) k_gemm3_heads(
    const float* __restrict__ in, const float* __restrict__ W,
    const float* __restrict__ b3,
    const float* __restrict__ Wopt, const float* __restrict__ bopt,
    const float* __restrict__ Wb1,  const float* __restrict__ bb1,
    const float* __restrict__ Wb2,  const float* __restrict__ bb2,
    float* __restrict__ out_opt, float* __restrict__ out_bot, int n)
{
    constexpr int K = 64, PAD = K + 1;
    __shared__ __align__(16) float Ws[K * H];
    __shared__ float xs[128 * PAD];
    __shared__ float bs[H];
    __shared__ u64  sWopt2[32 * 10];     // packed (2u, 2u+1) channel pairs
    __shared__ u64  sWb12 [32 * 32];
    __shared__ float sbopt[10], sbb1[32], sWb2[32], sbb2[1];
    __shared__ float sEmb[H];
    const int tid  = threadIdx.x;
    const int base = blockIdx.x * 128;

    for (int i = tid; i < K * H; i += 256) Ws[i] = W[i];
    for (int i = tid; i < 320; i += 256) {
        int u = i / 10, c = i - u * 10;
        sWopt2[i] = pack2(Wopt[(2*u) * 10 + c], Wopt[(2*u+1) * 10 + c]);
    }
    for (int i = tid; i < 1024; i += 256) {
        int u = i >> 5, m = i & 31;
        sWb12[i] = pack2(Wb1[(2*u) * 32 + m], Wb1[(2*u+1) * 32 + m]);
    }
    if (tid < H)  { bs[tid] = b3[tid]; sEmb[tid] = 0.f; }
    if (tid < 32) { sbb1[tid] = bb1[tid]; sWb2[tid] = Wb2[tid]; }
    if (tid < 10) sbopt[tid] = bopt[tid];
    if (tid == 0) sbb2[0] = bb2[0];

    int rows = n - base; if (rows > 128) rows = 128;
    for (int i = tid; i < rows * K; i += 256) {
        int r = i / K, c = i - r * K;
        xs[r * PAD + c] = in[(size_t)(base + r) * K + c];
    }
    __syncthreads();

    const int r     = tid >> 1;
    const bool valid = (r < rows);
    const int rc    = valid ? r : 0;
    const int half  = tid & 1;

    u64 acc2[16];
#pragma unroll
    for (int j = 0; j < 16; j++) acc2[j] = 0ull;

    const float* xrow = &xs[rc * PAD];
    const ulonglong2* w2 = (const ulonglong2*)Ws;
#pragma unroll 4
    for (int k = 0; k < K; k++) {
        float xv = xrow[k];
        u64 xv2 = pack2(xv, xv);
        const ulonglong2* wk = w2 + k * 16 + half;
#pragma unroll
        for (int j = 0; j < 8; j++) {
            ulonglong2 wv = wk[j * 2];
            acc2[2*j]   = fma2(xv2, wv.x, acc2[2*j]);
            acc2[2*j+1] = fma2(xv2, wv.y, acc2[2*j+1]);
        }
    }

    const int node = base + r;
    float d = valid ? g_dinv[node] : 0.f;

    // h3 = relu(d*acc + b3[ch]) (scalar), zero for invalid; then repack
    float acc[32];
#pragma unroll
    for (int j = 0; j < 16; j++) unpack2(acc2[j], acc[2*j], acc[2*j+1]);
#pragma unroll
    for (int j = 0; j < 8; j++) {
#pragma unroll
        for (int q = 0; q < 4; q++) {
            int ch = (j * 2 + half) * 4 + q;
            float v = fmaxf(fmaf(acc[4*j+q], d, bs[ch]), 0.f);
            acc[4*j+q] = valid ? v : 0.f;
        }
    }
#pragma unroll
    for (int j = 0; j < 16; j++) acc2[j] = pack2(acc[2*j], acc[2*j+1]);

    // opt logits: packed dots; pair index u = (i>>1)*4 + half*2 + (i&1)
#pragma unroll
    for (int c = 0; c < 10; c++) {
        u64 p2 = 0ull;
#pragma unroll
        for (int i = 0; i < 16; i++) {
            int u = (i >> 1) * 4 + half * 2 + (i & 1);
            p2 = fma2(acc2[i], sWopt2[u * 10 + c], p2);
        }
        float plo, phi; unpack2(p2, plo, phi);
        float p = plo + phi;
        p += __shfl_xor_sync(0xffffffffu, p, 1);
        if (valid && half == 0) out_opt[(size_t)node * 10 + c] = p + sbopt[c];
    }

    // bottleneck MLP: packed dots
    float z = 0.f;
#pragma unroll
    for (int m = 0; m < 32; m++) {
        u64 s2 = 0ull;
#pragma unroll
        for (int i = 0; i < 16; i++) {
            int u = (i >> 1) * 4 + half * 2 + (i & 1);
            s2 = fma2(acc2[i], sWb12[u * 32 + m], s2);
        }
        float slo, shi; unpack2(s2, slo, shi);
        float s = slo + shi;
        s += __shfl_xor_sync(0xffffffffu, s, 1);
        z = fmaf(fmaxf(s + sbb1[m], 0.f), sWb2[m], z);
    }
    if (valid && half == 0) out_bot[node] = 1.f / (1.f + expf(-(z + sbb2[0])));

    // embedding: parity-preserving warp reduce, then smem, then global
    const int lane = tid & 31;
#pragma unroll
    for (int idx = 0; idx < 32; idx++) {
        float v = acc[idx];
        v += __shfl_xor_sync(0xffffffffu, v, 2);
        v += __shfl_xor_sync(0xffffffffu, v, 4);
        v += __shfl_xor_sync(0xffffffffu, v, 8);
        v += __shfl_xor_sync(0xffffffffu, v, 16);
        if (lane < 2) {
            int ch = ((idx >> 2) * 2 + half) * 4 + (idx & 3);
            atomicAdd(&sEmb[ch], v);
        }
    }
    __syncthreads();
    if (tid < H) atomicAdd(&g_embed[tid], sEmb[tid]);
}

__global__ void k_embed_final(float* __restrict__ emb_out, float inv_n) {
    int t = threadIdx.x;
    if (t < H) {
        emb_out[t] = g_embed[t] * inv_n;
        g_embed[t] = 0.f;
    }
    if (t == 0) g_asmax = 0;
}

// ---------------- launcher ----------------
extern "C" void kernel_launch(void* const* d_in, const int* in_sizes, int n_in,
                              void* d_out, int out_size)
{
    const float* x    = (const float*)d_in[0];
    const int*   ei   = (const int*)  d_in[1];
    const float* W1   = (const float*)d_in[2];
    const float* b1   = (const float*)d_in[3];
    const float* W2   = (const float*)d_in[4];
    const float* avs  = (const float*)d_in[5];
    const float* avd  = (const float*)d_in[6];
    const float* b2   = (const float*)d_in[7];
    const float* W3   = (const float*)d_in[8];
    const float* b3   = (const float*)d_in[9];
    const float* Wopt = (const float*)d_in[10];
    const float* bopt = (const float*)d_in[11];
    const float* Wb1  = (const float*)d_in[12];
    const float* bb1  = (const float*)d_in[13];
    const float* Wb2  = (const float*)d_in[14];
    const float* bb2  = (const float*)d_in[15];

    const int n = in_sizes[0] / 32;   // F = 32
    const int e = in_sizes[1] / 2;
    const int* src = ei;
    const int* dst = ei + e;

    float* out_opt = (float*)d_out;
    float* out_bot = out_opt + (size_t)n * 10;
    float* out_emb = out_bot + n;

    float *bufA = nullptr, *bufB = nullptr, *t32 = nullptr;
    cudaGetSymbolAddress((void**)&bufA, g_bufA);
    cudaGetSymbolAddress((void**)&bufB, g_bufB);
    cudaGetSymbolAddress((void**)&t32,  g_t32);

    const int B = 256;
    const int gE4  = (e + 1023) / 1024;         // 4 edges/thread
    const int gN8  = (n * 8  + B - 1) / B;
    const int gN16 = (n * 16 + B - 1) / B;
    const int gG   = (n + 127) / 128;
    const int nb   = (n + 1023) / 1024;

    // CSR build
    k_deg<<<gE4, B>>>(dst, e);
    k_scanA<<<nb, 1024>>>(n);
    k_scanB<<<nb, 1024>>>(n, e);
    k_csr<<<gE4, B>>>(src, dst, e);

    // GCN layer 1: aggregate in F=32 space, then transform
    k_gather32<<<gN8, B>>>(x, t32, n);
    k_gemm<32, 0><<<gG, 256>>>(t32, W1, bufB, b1, nullptr, nullptr, n);

    // GAT layer (single-pass softmax via global as-max)
    k_gemm<64, 1><<<gG, 256>>>(bufB, W2, bufA, nullptr, avs, avd, n);
    k_gat_gather<<<gN16, B>>>(bufA, b2, bufB, n);

    // GCN layer 3: aggregate-first, then fused transform + heads
    k_gather64<<<gN16, B>>>(bufB, bufA, n);
    k_gemm3_heads<<<gG, 256>>>(bufA, W3, b3, Wopt, bopt, Wb1, bb1, Wb2, bb2,
                               out_opt, out_bot, n);

    k_embed_final<<<1, 64>>>(out_emb, 1.0f / (float)n);
}